// round 14
// baseline (speedup 1.0000x reference)
#include <cuda_runtime.h>
#include <cuda_bf16.h>
#include <cstdint>

// Problem constants
#define PB   128
#define PN   256
#define PD   1024
#define PH   16
#define PDK  64
#define PM   (PB*PN)   // 32768

// ---------------------------------------------------------------------------
// Global scratch
// ---------------------------------------------------------------------------
__device__ int8_t g_xq1[PM*PD], g_xq2[PM*PD];     // quantized inputs
__device__ int8_t g_xk1[PM*PD], g_xk2[PM*PD];
__device__ int8_t g_xv1[PM*PD], g_xv2[PM*PD];
__device__ int8_t g_oq1[PM*PD], g_oq2[PM*PD];     // quantized attn output
__device__ int8_t g_w1[4][PD*PD], g_w2[4][PD*PD]; // quantized weights
__device__ float  g_sxq[PM], g_sxk[PM], g_sxv[PM], g_so[PM];  // 2^-f row scales
__device__ float  g_sw[4][PD];

__device__ __nv_bfloat16 g_pq_h[PM*PD], g_pq_l[PM*PD];   // projection outputs
__device__ __nv_bfloat16 g_pk_h[PM*PD], g_pk_l[PM*PD];
__device__ __nv_bfloat16 g_pv_h[PM*PD], g_pv_l[PM*PD];
__device__ float g_O[PM*PD];                              // attn output fp32

// ---------------------------------------------------------------------------
// helpers
// ---------------------------------------------------------------------------
__device__ __forceinline__ uint32_t smem_u32(const void* p) {
    uint32_t a;
    asm("{ .reg .u64 t; cvta.to.shared.u64 t, %1; cvt.u32.u64 %0, t; }"
        : "=r"(a) : "l"(p));
    return a;
}
__device__ __forceinline__ uint32_t bf2(float x, float y) {
    uint32_t r;
    asm("cvt.rn.bf16x2.f32 %0, %2, %1;" : "=r"(r) : "f"(x), "f"(y));
    return r;
}
__device__ __forceinline__ void cpa16(uint32_t s, const void* g) {
    asm volatile("cp.async.cg.shared.global [%0], [%1], 16;"
                 :: "r"(s), "l"(g) : "memory");
}
__device__ __forceinline__ void ldsm4(uint32_t* r, uint32_t addr) {
    asm volatile("ldmatrix.sync.aligned.m8n8.x4.shared.b16 {%0,%1,%2,%3}, [%4];"
                 : "=r"(r[0]), "=r"(r[1]), "=r"(r[2]), "=r"(r[3]) : "r"(addr));
}
__device__ __forceinline__ void ldsm4t(uint32_t* r, uint32_t addr) {
    asm volatile("ldmatrix.sync.aligned.m8n8.x4.trans.shared.b16 {%0,%1,%2,%3}, [%4];"
                 : "=r"(r[0]), "=r"(r[1]), "=r"(r[2]), "=r"(r[3]) : "r"(addr));
}
__device__ __forceinline__ void mma_bf16(float* c, const uint32_t* a,
                                         const uint32_t* b) {
    asm volatile("mma.sync.aligned.m16n8k16.row.col.f32.bf16.bf16.f32 "
                 "{%0,%1,%2,%3}, {%4,%5,%6,%7}, {%8,%9}, {%0,%1,%2,%3};"
                 : "+f"(c[0]), "+f"(c[1]), "+f"(c[2]), "+f"(c[3])
                 : "r"(a[0]), "r"(a[1]), "r"(a[2]), "r"(a[3]),
                   "r"(b[0]), "r"(b[1]));
}
__device__ __forceinline__ void mma_s8(int* c, const uint32_t* a,
                                       const uint32_t* b) {
    asm volatile("mma.sync.aligned.m16n8k32.row.col.s32.s8.s8.s32 "
                 "{%0,%1,%2,%3}, {%4,%5,%6,%7}, {%8,%9}, {%0,%1,%2,%3};"
                 : "+r"(c[0]), "+r"(c[1]), "+r"(c[2]), "+r"(c[3])
                 : "r"(a[0]), "r"(a[1]), "r"(a[2]), "r"(a[3]),
                   "r"(b[0]), "r"(b[1]));
}

// fast exp on FMA/ALU pipes
__device__ __forceinline__ float fexp(float x) {
    x = fmaxf(x, -80.0f);
    float y = x * 1.44269504089f;
    float t = y + 12582912.0f;
    int   n = __float_as_int(t) - 0x4B400000;
    float fn = t - 12582912.0f;
    float f = y - fn;
    float r = fmaf(f, 1.3333558e-3f, 9.6181291e-3f);
    r = fmaf(f, r, 5.5504108e-2f);
    r = fmaf(f, r, 2.4022650e-1f);
    r = fmaf(f, r, 6.9314718e-1f);
    r = fmaf(f, r, 1.0f);
    float s = __int_as_float((n + 127) << 23);
    return r * s;
}

// ---------------------------------------------------------------------------
// quant: per row of PD fp32 -> two s8 slices + 2^-f scale.
// x*2^f = q1 + q2/128 + eps, f = 6 - ilogb(rowmax). One warp per row.
// ---------------------------------------------------------------------------
__global__ __launch_bounds__(256)
void quant_rows(const float* __restrict__ src, int8_t* __restrict__ q1,
                int8_t* __restrict__ q2, float* __restrict__ rs, int nrows)
{
    const int row  = blockIdx.x * 8 + (threadIdx.x >> 5);
    const int lane = threadIdx.x & 31;
    if (row >= nrows) return;
    const float4* s4 = (const float4*)(src + (size_t)row * PD);
    float4 v[8];
    float m = 0.f;
#pragma unroll
    for (int j = 0; j < 8; ++j) {
        v[j] = s4[lane + 32 * j];
        m = fmaxf(m, fmaxf(fmaxf(fabsf(v[j].x), fabsf(v[j].y)),
                           fmaxf(fabsf(v[j].z), fabsf(v[j].w))));
    }
#pragma unroll
    for (int o = 16; o; o >>= 1) m = fmaxf(m, __shfl_xor_sync(~0u, m, o));
    m = fmaxf(m, 1e-30f);
    int E = (__float_as_int(m) >> 23) & 255;
    int sbits = 260 - E;                       // biased exp of 2^(6-(E-127))
    sbits = max(1, min(254, sbits));
    const float scale = __int_as_float(sbits << 23);        // 2^f
    if (lane == 0) rs[row] = __int_as_float((254 - sbits) << 23); // 2^-f
    uint32_t* q1o = (uint32_t*)(q1 + (size_t)row * PD);
    uint32_t* q2o = (uint32_t*)(q2 + (size_t)row * PD);
#pragma unroll
    for (int j = 0; j < 8; ++j) {
        float xs[4] = {v[j].x, v[j].y, v[j].z, v[j].w};
        uint32_t p1 = 0, p2 = 0;
#pragma unroll
        for (int e = 0; e < 4; ++e) {
            float t = xs[e] * scale;           // exact (power-of-2 scale)
            int a = __float2int_rn(t);
            a = max(-127, min(127, a));
            float r = t - (float)a;            // exact
            int b = __float2int_rn(r * 128.f); // exact product
            b = max(-127, min(127, b));
            p1 |= (uint32_t)(a & 255) << (8 * e);
            p2 |= (uint32_t)(b & 255) << (8 * e);
        }
        q1o[lane + 32 * j] = p1;
        q2o[lane + 32 * j] = p2;
    }
}

// ---------------------------------------------------------------------------
// int8 GEMM: Y[m,e] = (sum_d A[m,d]*B[e,d] + bias[e]) * qscale.
// dot = (acc11 + accX/128 + acc22/16384) * ra[m] * rb[e].
// CTA 128x128, 256 threads (8 warps: 4m x 2n, warp tile 32x64), KC=64 (s8),
// 3-stage cp.async, same swizzle/ldsm addressing as proven bf16 kernel
// (s8 m16n8k32 fragments are byte-identical to bf16 m16n8k16 fragments).
// ---------------------------------------------------------------------------
#define GKC   64               // s8 elements per chunk (64 bytes/row)
#define GNK   (PD/GKC)         // 16 chunks
#define STGB  32768            // A1 8K | A2 8K | B1 8K | B2 8K
#define NSTG  3
#define GEMM_SMEM (NSTG*STGB)  // 96 KB

__device__ __forceinline__ uint32_t sw_off(int r, int c16) {
    return (uint32_t)(r * 64 + ((c16 ^ ((r >> 1) & 3)) << 4));
}

__device__ __forceinline__ void gemm_load_stage(
    uint32_t sbase, int stage, int kk, int tid,
    const int8_t* A1, const int8_t* A2,
    const int8_t* B1, const int8_t* B2)
{
    const uint32_t sb = sbase + (uint32_t)stage * STGB;
    const int koff = kk * GKC;
#pragma unroll
    for (int it = 0; it < 2; ++it) {
        int ch = tid + 256 * it;
        int r = ch >> 2, c = ch & 3;
        const size_t g = (size_t)r * PD + koff + c * 16;
        uint32_t so = sw_off(r, c);
        cpa16(sb + so,         A1 + g);
        cpa16(sb +  8192 + so, A2 + g);
        cpa16(sb + 16384 + so, B1 + g);
        cpa16(sb + 24576 + so, B2 + g);
    }
    asm volatile("cp.async.commit_group;" ::: "memory");
}

template<bool SPLIT>
__global__ __launch_bounds__(256, 1)
void gemm_s8(const int8_t* __restrict__ A1, const int8_t* __restrict__ A2,
             const int8_t* __restrict__ B1, const int8_t* __restrict__ B2,
             const float* __restrict__ ra, const float* __restrict__ rb,
             const float* __restrict__ bias, float qscale,
             float* __restrict__ Yf,
             __nv_bfloat16* __restrict__ Yh, __nv_bfloat16* __restrict__ Yl)
{
    extern __shared__ char smc[];
    const uint32_t sbase = smem_u32(smc);
    const int tid = threadIdx.x;
    const int wid = tid >> 5, lane = tid & 31;
    const int m0 = blockIdx.y * 128, n0 = blockIdx.x * 128;
    const int wm = wid & 3, wn = wid >> 2;   // 4m x 2n warps, tile 32x64

    const int8_t* A1p = A1 + (size_t)m0 * PD;
    const int8_t* A2p = A2 + (size_t)m0 * PD;
    const int8_t* B1p = B1 + (size_t)n0 * PD;
    const int8_t* B2p = B2 + (size_t)n0 * PD;

    int a11[2][8][4], aX[2][8][4], a22[2][8][4];
#pragma unroll
    for (int mi = 0; mi < 2; ++mi)
#pragma unroll
        for (int ni = 0; ni < 8; ++ni)
#pragma unroll
            for (int q = 0; q < 4; ++q) {
                a11[mi][ni][q] = 0; aX[mi][ni][q] = 0; a22[mi][ni][q] = 0;
            }

    gemm_load_stage(sbase, 0, 0, tid, A1p, A2p, B1p, B2p);
    gemm_load_stage(sbase, 1, 1, tid, A1p, A2p, B1p, B2p);

    const int a_row  = wm * 32 + (lane & 15);
    const int a_c16h = lane >> 4;
    const int b_row  = wn * 64 + ((lane >> 4) << 3) + (lane & 7);
    const int b_c16h = (lane >> 3) & 1;

    for (int kk = 0; kk < GNK; ++kk) {
        if (kk < GNK - 1) asm volatile("cp.async.wait_group 1;" ::: "memory");
        else              asm volatile("cp.async.wait_group 0;" ::: "memory");
        __syncthreads();

        if (kk + 2 < GNK)
            gemm_load_stage(sbase, (kk + 2) % NSTG, kk + 2, tid,
                            A1p, A2p, B1p, B2p);

        const uint32_t sb = sbase + (uint32_t)(kk % NSTG) * STGB;
#pragma unroll
        for (int ks = 0; ks < 2; ++ks) {       // two k32 steps per 64B row
            uint32_t aq1[2][4], aq2[2][4];
            const int ac = ks * 2 + a_c16h;
#pragma unroll
            for (int mi = 0; mi < 2; ++mi) {
                uint32_t so = sw_off(a_row + mi * 16, ac);
                ldsm4(aq1[mi], sb + so);
                ldsm4(aq2[mi], sb + 8192 + so);
            }
            const int bc = ks * 2 + b_c16h;
#pragma unroll
            for (int bi = 0; bi < 4; ++bi) {
                uint32_t bq1[4], bq2[4];
                uint32_t so = sw_off(b_row + bi * 16, bc);
                ldsm4(bq1, sb + 16384 + so);
                ldsm4(bq2, sb + 24576 + so);
#pragma unroll
                for (int mi = 0; mi < 2; ++mi)
#pragma unroll
                    for (int half = 0; half < 2; ++half) {
                        int ni = bi * 2 + half;
                        mma_s8(a11[mi][ni], aq1[mi], &bq1[half * 2]);
                        mma_s8(aX [mi][ni], aq2[mi], &bq1[half * 2]);
                        mma_s8(aX [mi][ni], aq1[mi], &bq2[half * 2]);
                        mma_s8(a22[mi][ni], aq2[mi], &bq2[half * 2]);
                    }
            }
        }
    }

    // epilogue
    const int trow = lane >> 2;
    const int tcol = (lane & 3) * 2;
#pragma unroll
    for (int mi = 0; mi < 2; ++mi) {
#pragma unroll
        for (int rr = 0; rr < 2; ++rr) {
            const int r0 = m0 + wm * 32 + mi * 16 + rr * 8 + trow;
            const float sa = ra[r0];
#pragma unroll
            for (int ni = 0; ni < 8; ++ni) {
                const int col = n0 + wn * 64 + ni * 8 + tcol;
                float d0 = (float)a11[mi][ni][rr*2+0]
                         + (float)aX [mi][ni][rr*2+0] * 0.0078125f
                         + (float)a22[mi][ni][rr*2+0] * 6.103515625e-05f;
                float d1 = (float)a11[mi][ni][rr*2+1]
                         + (float)aX [mi][ni][rr*2+1] * 0.0078125f
                         + (float)a22[mi][ni][rr*2+1] * 6.103515625e-05f;
                float f0 = (d0 * sa * rb[col]     + bias[col])     * qscale;
                float f1 = (d1 * sa * rb[col + 1] + bias[col + 1]) * qscale;
                if (SPLIT) {
                    uint32_t hh = bf2(f0, f1);
                    float e0 = f0 - __uint_as_float(hh << 16);
                    float e1 = f1 - __uint_as_float(hh & 0xffff0000u);
                    *(uint32_t*)(Yh + (size_t)r0 * PD + col) = hh;
                    *(uint32_t*)(Yl + (size_t)r0 * PD + col) = bf2(e0, e1);
                } else {
                    *(float2*)(Yf + (size_t)r0 * PD + col) = make_float2(f0, f1);
                }
            }
        }
    }
}

// ---------------------------------------------------------------------------
// Tensor-core attention (proven bf16x3 path): one CTA per (h,n), 256 threads.
// Inputs pre-split bf16 hi/lo (Q pre-scaled 1/8). Output: fp32.
// ---------------------------------------------------------------------------
#define AT_PITCH   144
#define AT_PPITCH  272
#define AT_QH      0
#define AT_QL      18432
#define AT_KH      36864
#define AT_KL      55296
#define AT_VH      73728
#define AT_VL      92160
#define AT_RED     110592
#define AT_RED2    111616
#define AT_SMEM    112640
#define AT_PH      0
#define AT_PL      34816

__global__ __launch_bounds__(256)
void attn_tc(const __nv_bfloat16* __restrict__ Qh, const __nv_bfloat16* __restrict__ Ql,
             const __nv_bfloat16* __restrict__ Kh, const __nv_bfloat16* __restrict__ Kl,
             const __nv_bfloat16* __restrict__ Vh, const __nv_bfloat16* __restrict__ Vl,
             float* __restrict__ O)
{
    extern __shared__ char sm[];
    const uint32_t sb = smem_u32(sm);
    const int tid = threadIdx.x;
    const int wid = tid >> 5, lane = tid & 31;
    const int wm = wid & 3, wn = wid >> 2;
    const int hn = blockIdx.x;
    const int h  = hn >> 8;
    const int n  = hn & 255;
    const size_t rowoff = (size_t)n * PD + h * PDK;

#define AT_LOADHALF(SRC, BASE)                                              \
    {                                                                       \
        _Pragma("unroll")                                                   \
        for (int j = 0; j < 4; ++j) {                                       \
            int i = tid + 256 * j;                                          \
            int r = i >> 3, c = i & 7;                                      \
            uint4 v = *(const uint4*)((SRC) + (size_t)r * (PD * PN)         \
                                      + rowoff + c * 8);                    \
            *(uint4*)(sm + (BASE) + r * AT_PITCH + c * 16) = v;             \
        }                                                                   \
    }
    AT_LOADHALF(Qh, AT_QH)
    AT_LOADHALF(Ql, AT_QL)
    AT_LOADHALF(Kh, AT_KH)
    AT_LOADHALF(Kl, AT_KL)
    AT_LOADHALF(Vh, AT_VH)
    AT_LOADHALF(Vl, AT_VL)
#undef AT_LOADHALF
    __syncthreads();

    float sc[2][8][4];
#pragma unroll
    for (int mi = 0; mi < 2; ++mi)
#pragma unroll
        for (int ni = 0; ni < 8; ++ni)
#pragma unroll
            for (int q = 0; q < 4; ++q) sc[mi][ni][q] = 0.f;

    const int a_row = wm * 32 + (lane & 15);
    const int a_off = (lane >> 4) * 16;
    const int b_row = wn * 64 + ((lane >> 4) << 3) + (lane & 7);
    const int b_off = ((lane >> 3) & 1) * 16;

#pragma unroll
    for (int ks = 0; ks < 4; ++ks) {
        uint32_t ah[2][4], al[2][4];
#pragma unroll
        for (int mi = 0; mi < 2; ++mi) {
            uint32_t ad = sb + (uint32_t)((a_row + mi * 16) * AT_PITCH + ks * 32) + a_off;
            ldsm4(ah[mi], ad + AT_QH);
            ldsm4(al[mi], ad + AT_QL);
        }
#pragma unroll
        for (int bi = 0; bi < 4; ++bi) {
            uint32_t bh[4], bl[4];
            uint32_t bd = sb + (uint32_t)((b_row + bi * 16) * AT_PITCH + ks * 32) + b_off;
            ldsm4(bh, bd + AT_KH);
            ldsm4(bl, bd + AT_KL);
#pragma unroll
            for (int mi = 0; mi < 2; ++mi)
#pragma unroll
                for (int half = 0; half < 2; ++half) {
                    float* c4 = sc[mi][bi * 2 + half];
                    mma_bf16(c4, ah[mi], &bh[half * 2]);
                    mma_bf16(c4, ah[mi], &bl[half * 2]);
                    mma_bf16(c4, al[mi], &bh[half * 2]);
                }
        }
    }

    const int trow = lane >> 2;
    const int tcol = (lane & 3) * 2;
    float* red  = (float*)(sm + AT_RED);
    float* red2 = (float*)(sm + AT_RED2);

#pragma unroll
    for (int mi = 0; mi < 2; ++mi)
#pragma unroll
        for (int hr = 0; hr < 2; ++hr) {
            float m = -1e30f;
#pragma unroll
            for (int ni = 0; ni < 8; ++ni) {
                m = fmaxf(m, sc[mi][ni][hr * 2 + 0]);
                m = fmaxf(m, sc[mi][ni][hr * 2 + 1]);
            }
            m = fmaxf(m, __shfl_xor_sync(0xffffffffu, m, 1));
            m = fmaxf(m, __shfl_xor_sync(0xffffffffu, m, 2));
            int row = wm * 32 + mi * 16 + hr * 8 + trow;
            if ((lane & 3) == 0) red[row * 2 + wn] = m;
        }
    __syncthreads();

    float inv_[2][2];
#pragma unroll
    for (int mi = 0; mi < 2; ++mi)
#pragma unroll
        for (int hr = 0; hr < 2; ++hr) {
            int row = wm * 32 + mi * 16 + hr * 8 + trow;
            float m2 = fmaxf(red[row * 2], red[row * 2 + 1]);
            float ls = 0.f;
#pragma unroll
            for (int ni = 0; ni < 8; ++ni) {
                float e0 = fexp(sc[mi][ni][hr * 2 + 0] - m2);
                float e1 = fexp(sc[mi][ni][hr * 2 + 1] - m2);
                sc[mi][ni][hr * 2 + 0] = e0;
                sc[mi][ni][hr * 2 + 1] = e1;
                ls += e0 + e1;
            }
            ls += __shfl_xor_sync(0xffffffffu, ls, 1);
            ls += __shfl_xor_sync(0xffffffffu, ls, 2);
            if ((lane & 3) == 0) red2[row * 2 + wn] = ls;
        }
    __syncthreads();

#pragma unroll
    for (int mi = 0; mi < 2; ++mi)
#pragma unroll
        for (int hr = 0; hr < 2; ++hr) {
            int row = wm * 32 + mi * 16 + hr * 8 + trow;
            inv_[mi][hr] = 1.0f / (red2[row * 2] + red2[row * 2 + 1]);
        }

#pragma unroll
    for (int mi = 0; mi < 2; ++mi)
#pragma unroll
        for (int hr = 0; hr < 2; ++hr) {
            int row = wm * 32 + mi * 16 + hr * 8 + trow;
            uint32_t pb = sb + (uint32_t)(row * AT_PPITCH);
#pragma unroll
            for (int ni = 0; ni < 8; ++ni) {
                float e0 = sc[mi][ni][hr * 2 + 0];
                float e1 = sc[mi][ni][hr * 2 + 1];
                uint32_t hh = bf2(e0, e1);
                float r0 = e0 - __uint_as_float(hh << 16);
                float r1 = e1 - __uint_as_float(hh & 0xffff0000u);
                uint32_t ll = bf2(r0, r1);
                int colB = (wn * 64 + ni * 8 + tcol) * 2;
                asm volatile("st.shared.u32 [%0], %1;" :: "r"(pb + AT_PH + colB), "r"(hh) : "memory");
                asm volatile("st.shared.u32 [%0], %1;" :: "r"(pb + AT_PL + colB), "r"(ll) : "memory");
            }
        }
    __syncthreads();

    float oc[2][4][4];
#pragma unroll
    for (int mi = 0; mi < 2; ++mi)
#pragma unroll
        for (int ni = 0; ni < 4; ++ni)
#pragma unroll
            for (int q = 0; q < 4; ++q) oc[mi][ni][q] = 0.f;

    const int vrow_l = (lane & 7) + ((lane >> 3) & 1) * 8;
    const int vcol_l = wn * 64 + ((lane >> 4) & 1) * 16;

#pragma unroll
    for (int ks = 0; ks < 8; ++ks) {
        uint32_t ph[2][4], pl[2][4];
#pragma unroll
        for (int mi = 0; mi < 2; ++mi) {
            uint32_t ad = sb + (uint32_t)((a_row + mi * 16) * AT_PPITCH + ks * 32) + a_off;
            ldsm4(ph[mi], ad + AT_PH);
            ldsm4(pl[mi], ad + AT_PL);
        }
#pragma unroll
        for (int p = 0; p < 2; ++p) {
            uint32_t vh4[4], vl4[4];
            uint32_t vd = sb + (uint32_t)((ks * 16 + vrow_l) * AT_PITCH) + vcol_l + p * 32;
            ldsm4t(vh4, vd + AT_VH);
            ldsm4t(vl4, vd + AT_VL);
#pragma unroll
            for (int mi = 0; mi < 2; ++mi)
#pragma unroll
                for (int half = 0; half < 2; ++half) {
                    float* c4 = oc[mi][p * 2 + half];
                    mma_bf16(c4, ph[mi], &vh4[half * 2]);
                    mma_bf16(c4, ph[mi], &vl4[half * 2]);
                    mma_bf16(c4, pl[mi], &vh4[half * 2]);
                }
        }
    }

#pragma unroll
    for (int mi = 0; mi < 2; ++mi)
#pragma unroll
        for (int hr = 0; hr < 2; ++hr) {
            int row = wm * 32 + mi * 16 + hr * 8 + trow;
            float iv = inv_[mi][hr];
            size_t ob = ((size_t)row * PN + n) * PD + h * PDK;
#pragma unroll
            for (int ni = 0; ni < 4; ++ni) {
                int col = wn * 32 + ni * 8 + tcol;
                float f0 = oc[mi][ni][hr * 2 + 0] * iv;
                float f1 = oc[mi][ni][hr * 2 + 1] * iv;
                *(float2*)(O + ob + col) = make_float2(f0, f1);
            }
        }
}

// ---------------------------------------------------------------------------
extern "C" void kernel_launch(void* const* d_in, const int* in_sizes, int n_in,
                              void* d_out, int out_size)
{
    const float* query = (const float*)d_in[0];
    const float* key_i = (const float*)d_in[1];
    const float* value = (const float*)d_in[2];
    const float* Wq = (const float*)d_in[3];
    const float* bq = (const float*)d_in[4];
    const float* Wk = (const float*)d_in[5];
    const float* bk = (const float*)d_in[6];
    const float* Wv = (const float*)d_in[7];
    const float* bv = (const float*)d_in[8];
    const float* Wo = (const float*)d_in[9];
    const float* bo = (const float*)d_in[10];
    float* out = (float*)d_out;

    int8_t *xq1, *xq2, *xk1, *xk2, *xv1, *xv2, *oq1, *oq2, *w1, *w2;
    float *sxq, *sxk, *sxv, *so, *sw, *O;
    __nv_bfloat16 *pqh, *pql, *pkh, *pkl, *pvh, *pvl;
    cudaGetSymbolAddress((void**)&xq1, g_xq1);
    cudaGetSymbolAddress((void**)&xq2, g_xq2);
    cudaGetSymbolAddress((void**)&xk1, g_xk1);
    cudaGetSymbolAddress((void**)&xk2, g_xk2);
    cudaGetSymbolAddress((void**)&xv1, g_xv1);
    cudaGetSymbolAddress((void**)&xv2, g_xv2);
    cudaGetSymbolAddress((void**)&oq1, g_oq1);
    cudaGetSymbolAddress((void**)&oq2, g_oq2);
    cudaGetSymbolAddress((void**)&w1,  g_w1);
    cudaGetSymbolAddress((void**)&w2,  g_w2);
    cudaGetSymbolAddress((void**)&sxq, g_sxq);
    cudaGetSymbolAddress((void**)&sxk, g_sxk);
    cudaGetSymbolAddress((void**)&sxv, g_sxv);
    cudaGetSymbolAddress((void**)&so,  g_so);
    cudaGetSymbolAddress((void**)&sw,  g_sw);
    cudaGetSymbolAddress((void**)&O,   g_O);
    cudaGetSymbolAddress((void**)&pqh, g_pq_h);
    cudaGetSymbolAddress((void**)&pql, g_pq_l);
    cudaGetSymbolAddress((void**)&pkh, g_pk_h);
    cudaGetSymbolAddress((void**)&pkl, g_pk_l);
    cudaGetSymbolAddress((void**)&pvh, g_pv_h);
    cudaGetSymbolAddress((void**)&pvl, g_pv_l);

    cudaFuncSetAttribute(gemm_s8<true>,
                         cudaFuncAttributeMaxDynamicSharedMemorySize, GEMM_SMEM);
    cudaFuncSetAttribute(gemm_s8<false>,
                         cudaFuncAttributeMaxDynamicSharedMemorySize, GEMM_SMEM);
    cudaFuncSetAttribute(attn_tc,
                         cudaFuncAttributeMaxDynamicSharedMemorySize, AT_SMEM);

    dim3 gg(PD / 128, PM / 128);   // (8, 256)
    const size_t WSZ = (size_t)PD * PD;

    quant_rows<<<PM / 8, 256>>>(query, xq1, xq2, sxq, PM);
    quant_rows<<<PD / 8, 256>>>(Wq, w1 + 0 * WSZ, w2 + 0 * WSZ, sw + 0 * PD, PD);
    quant_rows<<<PM / 8, 256>>>(key_i, xk1, xk2, sxk, PM);
    quant_rows<<<PD / 8, 256>>>(Wk, w1 + 1 * WSZ, w2 + 1 * WSZ, sw + 1 * PD, PD);
    quant_rows<<<PM / 8, 256>>>(value, xv1, xv2, sxv, PM);

    gemm_s8<true><<<gg, 256, GEMM_SMEM>>>(
        xq1, xq2, w1 + 0 * WSZ, w2 + 0 * WSZ, sxq, sw + 0 * PD,
        bq, 0.125f, nullptr, pqh, pql);

    quant_rows<<<PD / 8, 256>>>(Wv, w1 + 2 * WSZ, w2 + 2 * WSZ, sw + 2 * PD, PD);
    quant_rows<<<PD / 8, 256>>>(Wo, w1 + 3 * WSZ, w2 + 3 * WSZ, sw + 3 * PD, PD);

    gemm_s8<true><<<gg, 256, GEMM_SMEM>>>(
        xk1, xk2, w1 + 1 * WSZ, w2 + 1 * WSZ, sxk, sw + 1 * PD,
        bk, 1.0f, nullptr, pkh, pkl);
    gemm_s8<true><<<gg, 256, GEMM_SMEM>>>(
        xv1, xv2, w1 + 2 * WSZ, w2 + 2 * WSZ, sxv, sw + 2 * PD,
        bv, 1.0f, nullptr, pvh, pvl);

    attn_tc<<<PH * PN, 256, AT_SMEM>>>(pqh, pql, pkh, pkl, pvh, pvl, O);

    quant_rows<<<PM / 8, 256>>>(O, oq1, oq2, so, PM);

    gemm_s8<false><<<gg, 256, GEMM_SMEM>>>(
        oq1, oq2, w1 + 3 * WSZ, w2 + 3 * WSZ, so, sw + 3 * PD,
        bo, 1.0f, out, nullptr, nullptr);
}

// round 16
// speedup vs baseline: 3.5944x; 3.5944x over previous
#include <cuda_runtime.h>
#include <cuda_bf16.h>
#include <cstdint>

// Problem constants
#define PB   128
#define PN   256
#define PD   1024
#define PH   16
#define PDK  64
#define PM   (PB*PN)   // 32768

// ---------------------------------------------------------------------------
// Global scratch (bf16 hi/lo pairs everywhere; no fp32 intermediates)
// ---------------------------------------------------------------------------
__device__ __nv_bfloat16 g_xq_h[PM*PD], g_xq_l[PM*PD];   // input splits
__device__ __nv_bfloat16 g_xk_h[PM*PD], g_xk_l[PM*PD];
__device__ __nv_bfloat16 g_xv_h[PM*PD], g_xv_l[PM*PD];
__device__ __nv_bfloat16 g_pq_h[PM*PD], g_pq_l[PM*PD];   // projection outputs
__device__ __nv_bfloat16 g_pk_h[PM*PD], g_pk_l[PM*PD];
__device__ __nv_bfloat16 g_pv_h[PM*PD], g_pv_l[PM*PD];
__device__ __nv_bfloat16 g_o_h[PM*PD],  g_o_l[PM*PD];    // attention output
__device__ __nv_bfloat16 g_wh[4][PD*PD], g_wl[4][PD*PD]; // weight splits

// ---------------------------------------------------------------------------
// helpers
// ---------------------------------------------------------------------------
__device__ __forceinline__ uint32_t smem_u32(const void* p) {
    uint32_t a;
    asm("{ .reg .u64 t; cvta.to.shared.u64 t, %1; cvt.u32.u64 %0, t; }"
        : "=r"(a) : "l"(p));
    return a;
}
__device__ __forceinline__ uint32_t bf2(float x, float y) {
    uint32_t r;
    asm("cvt.rn.bf16x2.f32 %0, %2, %1;" : "=r"(r) : "f"(x), "f"(y));
    return r;
}
__device__ __forceinline__ void cpa16(uint32_t s, const void* g) {
    asm volatile("cp.async.cg.shared.global [%0], [%1], 16;"
                 :: "r"(s), "l"(g) : "memory");
}
__device__ __forceinline__ void ldsm4(uint32_t* r, uint32_t addr) {
    asm volatile("ldmatrix.sync.aligned.m8n8.x4.shared.b16 {%0,%1,%2,%3}, [%4];"
                 : "=r"(r[0]), "=r"(r[1]), "=r"(r[2]), "=r"(r[3]) : "r"(addr));
}
__device__ __forceinline__ void ldsm4t(uint32_t* r, uint32_t addr) {
    asm volatile("ldmatrix.sync.aligned.m8n8.x4.trans.shared.b16 {%0,%1,%2,%3}, [%4];"
                 : "=r"(r[0]), "=r"(r[1]), "=r"(r[2]), "=r"(r[3]) : "r"(addr));
}
__device__ __forceinline__ void mma_bf16(float* c, const uint32_t* a,
                                         const uint32_t* b) {
    asm volatile("mma.sync.aligned.m16n8k16.row.col.f32.bf16.bf16.f32 "
                 "{%0,%1,%2,%3}, {%4,%5,%6,%7}, {%8,%9}, {%0,%1,%2,%3};"
                 : "+f"(c[0]), "+f"(c[1]), "+f"(c[2]), "+f"(c[3])
                 : "r"(a[0]), "r"(a[1]), "r"(a[2]), "r"(a[3]),
                   "r"(b[0]), "r"(b[1]));
}

// fast exp on FMA/ALU pipes (avoids MUFU rt=8 floor)
__device__ __forceinline__ float fexp(float x) {
    x = fmaxf(x, -80.0f);
    float y = x * 1.44269504089f;
    float t = y + 12582912.0f;
    int   n = __float_as_int(t) - 0x4B400000;
    float fn = t - 12582912.0f;
    float f = y - fn;
    float r = fmaf(f, 1.3333558e-3f, 9.6181291e-3f);
    r = fmaf(f, r, 5.5504108e-2f);
    r = fmaf(f, r, 2.4022650e-1f);
    r = fmaf(f, r, 6.9314718e-1f);
    r = fmaf(f, r, 1.0f);
    float s = __int_as_float((n + 127) << 23);
    return r * s;
}

// ---------------------------------------------------------------------------
// split helpers: fp32 -> bf16 hi + bf16 lo (residual)
// ---------------------------------------------------------------------------
__device__ __forceinline__ void split_one(const float* __restrict__ src,
                                          __nv_bfloat16* __restrict__ hi,
                                          __nv_bfloat16* __restrict__ lo,
                                          int i0, int stride)
{
    float4 v[4];
#pragma unroll
    for (int j = 0; j < 4; ++j) v[j] = ((const float4*)src)[i0 + j * stride];
#pragma unroll
    for (int j = 0; j < 4; ++j) {
        int i = i0 + j * stride;
        uint32_t h01 = bf2(v[j].x, v[j].y);
        uint32_t h23 = bf2(v[j].z, v[j].w);
        float r0 = v[j].x - __uint_as_float(h01 << 16);
        float r1 = v[j].y - __uint_as_float(h01 & 0xffff0000u);
        float r2 = v[j].z - __uint_as_float(h23 << 16);
        float r3 = v[j].w - __uint_as_float(h23 & 0xffff0000u);
        ((uint2*)hi)[i] = make_uint2(h01, h23);
        ((uint2*)lo)[i] = make_uint2(bf2(r0, r1), bf2(r2, r3));
    }
}

// batched input split: z selects {query, key, value}
__global__ __launch_bounds__(256)
void split_inputs(const float* __restrict__ q, const float* __restrict__ k,
                  const float* __restrict__ v,
                  __nv_bfloat16* __restrict__ qh, __nv_bfloat16* __restrict__ ql,
                  __nv_bfloat16* __restrict__ kh, __nv_bfloat16* __restrict__ kl,
                  __nv_bfloat16* __restrict__ vh, __nv_bfloat16* __restrict__ vl)
{
    const int stride = gridDim.x * 256;
    const int i0 = blockIdx.x * 256 + threadIdx.x;
    const int z = blockIdx.z;
    const float* src = (z == 0) ? q : (z == 1) ? k : v;
    __nv_bfloat16* hi = (z == 0) ? qh : (z == 1) ? kh : vh;
    __nv_bfloat16* lo = (z == 0) ? ql : (z == 1) ? kl : vl;
    split_one(src, hi, lo, i0, stride);
}

// batched weight split: z selects {Wq, Wk, Wv, Wo}
__global__ __launch_bounds__(256)
void split_weights(const float* __restrict__ w0, const float* __restrict__ w1,
                   const float* __restrict__ w2, const float* __restrict__ w3,
                   __nv_bfloat16* __restrict__ wh, __nv_bfloat16* __restrict__ wl)
{
    const int stride = gridDim.x * 256;
    const int i0 = blockIdx.x * 256 + threadIdx.x;
    const int z = blockIdx.z;
    const float* src = (z == 0) ? w0 : (z == 1) ? w1 : (z == 2) ? w2 : w3;
    split_one(src, wh + (size_t)z * PD * PD, wl + (size_t)z * PD * PD,
              i0, stride);
}

// ---------------------------------------------------------------------------
// GEMM: Y[m,e] = (sum_d A[m,d]*B[e,d] + bias[e]) * scale, 3-term bf16 split.
// CTA tile 128x128, 128 threads (4 warps: 2m x 2n, warp tile 64x64), KC=32,
// 3-stage cp.async pipeline, 32KB/stage -> 96KB smem -> 2 CTAs/SM.
// At the measured bf16 HMMA wall (~10.7 cyc/HMMA/SMSP).
// ---------------------------------------------------------------------------
#define GKC   32
#define GNK   (PD/GKC)          // 32 chunks
#define STGB  32768             // per-stage: Ah 8K | Al 8K | Bh 8K | Bl 8K
#define NSTG  3
#define GEMM_SMEM (NSTG*STGB)   // 96 KB

__device__ __forceinline__ uint32_t sw_off(int r, int c16) {
    return (uint32_t)(r * 64 + ((c16 ^ ((r >> 1) & 3)) << 4));
}

__device__ __forceinline__ void gemm_load_stage(
    uint32_t sbase, int stage, int kk, int tid,
    const __nv_bfloat16* Ah0, const __nv_bfloat16* Al0,
    const __nv_bfloat16* Bh0, const __nv_bfloat16* Bl0)
{
    const uint32_t sb = sbase + (uint32_t)stage * STGB;
    const int koff = kk * GKC;
#pragma unroll
    for (int it = 0; it < 4; ++it) {
        int ch = tid + 128 * it;
        int r = ch >> 2, c = ch & 3;
        const size_t g = (size_t)r * PD + koff + c * 8;
        uint32_t so = sw_off(r, c);
        cpa16(sb + so,         Ah0 + g);
        cpa16(sb +  8192 + so, Al0 + g);
        cpa16(sb + 16384 + so, Bh0 + g);
        cpa16(sb + 24576 + so, Bl0 + g);
    }
    asm volatile("cp.async.commit_group;" ::: "memory");
}

template<bool SPLIT>
__global__ __launch_bounds__(128, 2)
void gemm_bf16x3(const __nv_bfloat16* __restrict__ Ah,
                 const __nv_bfloat16* __restrict__ Al,
                 const __nv_bfloat16* __restrict__ Bh,
                 const __nv_bfloat16* __restrict__ Bl,
                 const float* __restrict__ bias, float scale,
                 float* __restrict__ Yf,
                 __nv_bfloat16* __restrict__ Yh,
                 __nv_bfloat16* __restrict__ Yl)
{
    extern __shared__ char smc[];
    const uint32_t sbase = smem_u32(smc);
    const int tid = threadIdx.x;
    const int wid = tid >> 5, lane = tid & 31;
    const int m0 = blockIdx.y * 128, n0 = blockIdx.x * 128;
    const int wm = wid & 1, wn = wid >> 1;   // 2m x 2n warps, each 64x64

    const __nv_bfloat16* Ah0 = Ah + (size_t)m0 * PD;
    const __nv_bfloat16* Al0 = Al + (size_t)m0 * PD;
    const __nv_bfloat16* Bh0 = Bh + (size_t)n0 * PD;
    const __nv_bfloat16* Bl0 = Bl + (size_t)n0 * PD;

    float acc[4][8][4];
#pragma unroll
    for (int mi = 0; mi < 4; ++mi)
#pragma unroll
        for (int ni = 0; ni < 8; ++ni)
#pragma unroll
            for (int q = 0; q < 4; ++q) acc[mi][ni][q] = 0.f;

    gemm_load_stage(sbase, 0, 0, tid, Ah0, Al0, Bh0, Bl0);
    gemm_load_stage(sbase, 1, 1, tid, Ah0, Al0, Bh0, Bl0);

    const int a_row  = wm * 64 + (lane & 15);
    const int a_c16h = lane >> 4;
    const int b_row  = wn * 64 + ((lane >> 4) << 3) + (lane & 7);
    const int b_c16h = (lane >> 3) & 1;

    for (int kk = 0; kk < GNK; ++kk) {
        if (kk < GNK - 1) asm volatile("cp.async.wait_group 1;" ::: "memory");
        else              asm volatile("cp.async.wait_group 0;" ::: "memory");
        __syncthreads();

        if (kk + 2 < GNK)
            gemm_load_stage(sbase, (kk + 2) % NSTG, kk + 2, tid, Ah0, Al0, Bh0, Bl0);

        const uint32_t sb = sbase + (uint32_t)(kk % NSTG) * STGB;
#pragma unroll
        for (int ks = 0; ks < 2; ++ks) {
            uint32_t ahi[4][4], alo[4][4], bhi[4][4], blo[4][4];
            const int ac = ks * 2 + a_c16h;
            const int bc = ks * 2 + b_c16h;
#pragma unroll
            for (int mi = 0; mi < 4; ++mi) {
                uint32_t so = sw_off(a_row + mi * 16, ac);
                ldsm4(ahi[mi], sb + so);
                ldsm4(alo[mi], sb + 8192 + so);
            }
#pragma unroll
            for (int bi = 0; bi < 4; ++bi) {
                uint32_t so = sw_off(b_row + bi * 16, bc);
                ldsm4(bhi[bi], sb + 16384 + so);
                ldsm4(blo[bi], sb + 24576 + so);
            }
#pragma unroll
            for (int bi = 0; bi < 4; ++bi)
#pragma unroll
                for (int mi = 0; mi < 4; ++mi)
#pragma unroll
                    for (int half = 0; half < 2; ++half) {
                        float* c4 = acc[mi][bi * 2 + half];
                        mma_bf16(c4, ahi[mi], &bhi[bi][half * 2]);
                        mma_bf16(c4, ahi[mi], &blo[bi][half * 2]);
                        mma_bf16(c4, alo[mi], &bhi[bi][half * 2]);
                    }
        }
    }

    // epilogue: thread t -> rows (t/4, t/4+8), cols (t%4)*2, +1
    const int trow = lane >> 2;
    const int tcol = (lane & 3) * 2;
#pragma unroll
    for (int mi = 0; mi < 4; ++mi) {
#pragma unroll
        for (int rr = 0; rr < 2; ++rr) {
            const int r0 = m0 + wm * 64 + mi * 16 + rr * 8 + trow;
#pragma unroll
            for (int ni = 0; ni < 8; ++ni) {
                const int col = n0 + wn * 64 + ni * 8 + tcol;
                float* c4 = acc[mi][ni];
                float f0 = (c4[rr * 2 + 0] + bias[col])     * scale;
                float f1 = (c4[rr * 2 + 1] + bias[col + 1]) * scale;
                if (SPLIT) {
                    uint32_t hh = bf2(f0, f1);
                    float e0 = f0 - __uint_as_float(hh << 16);
                    float e1 = f1 - __uint_as_float(hh & 0xffff0000u);
                    *(uint32_t*)(Yh + (size_t)r0 * PD + col) = hh;
                    *(uint32_t*)(Yl + (size_t)r0 * PD + col) = bf2(e0, e1);
                } else {
                    *(float2*)(Yf + (size_t)r0 * PD + col) = make_float2(f0, f1);
                }
            }
        }
    }
}

// ---------------------------------------------------------------------------
// Tensor-core attention: one CTA per (h,n), 256 threads (8 warps: 4m x 2n).
// Inputs arrive pre-split bf16 hi/lo (Q pre-scaled by 1/8 in its GEMM).
// ---------------------------------------------------------------------------
#define AT_PITCH   144           // rows: 64 bf16 = 128B + 16 pad
#define AT_PPITCH  272           // P rows: 128 bf16 = 256B + 16 pad
#define AT_QH      0
#define AT_QL      18432
#define AT_KH      36864
#define AT_KL      55296
#define AT_VH      73728
#define AT_VL      92160
#define AT_RED     110592
#define AT_RED2    111616
#define AT_SMEM    112640
#define AT_PH      0             // P reuses dead Q/K region
#define AT_PL      34816

__global__ __launch_bounds__(256)
void attn_tc(const __nv_bfloat16* __restrict__ Qh, const __nv_bfloat16* __restrict__ Ql,
             const __nv_bfloat16* __restrict__ Kh, const __nv_bfloat16* __restrict__ Kl,
             const __nv_bfloat16* __restrict__ Vh, const __nv_bfloat16* __restrict__ Vl,
             __nv_bfloat16* __restrict__ Oh, __nv_bfloat16* __restrict__ Ol)
{
    extern __shared__ char sm[];
    const uint32_t sb = smem_u32(sm);
    const int tid = threadIdx.x;
    const int wid = tid >> 5, lane = tid & 31;
    const int wm = wid & 3, wn = wid >> 2;   // 4m x 2n
    const int hn = blockIdx.x;
    const int h  = hn >> 8;
    const int n  = hn & 255;
    const size_t rowoff = (size_t)n * PD + h * PDK;

    // ---- gather pre-split bf16 tiles ----
#define AT_LOADHALF(SRC, BASE)                                              \
    {                                                                       \
        _Pragma("unroll")                                                   \
        for (int j = 0; j < 4; ++j) {                                       \
            int i = tid + 256 * j;                                          \
            int r = i >> 3, c = i & 7;                                      \
            uint4 v = *(const uint4*)((SRC) + (size_t)r * (PD * PN)         \
                                      + rowoff + c * 8);                    \
            *(uint4*)(sm + (BASE) + r * AT_PITCH + c * 16) = v;             \
        }                                                                   \
    }
    AT_LOADHALF(Qh, AT_QH)
    AT_LOADHALF(Ql, AT_QL)
    AT_LOADHALF(Kh, AT_KH)
    AT_LOADHALF(Kl, AT_KL)
    AT_LOADHALF(Vh, AT_VH)
    AT_LOADHALF(Vl, AT_VL)
#undef AT_LOADHALF
    __syncthreads();

    // ---- scores: S = Qs * K^T  (M=128, N=128, K=64), 3-term ----
    float sc[2][8][4];
#pragma unroll
    for (int mi = 0; mi < 2; ++mi)
#pragma unroll
        for (int ni = 0; ni < 8; ++ni)
#pragma unroll
            for (int q = 0; q < 4; ++q) sc[mi][ni][q] = 0.f;

    const int a_row = wm * 32 + (lane & 15);
    const int a_off = (lane >> 4) * 16;                          // bytes
    const int b_row = wn * 64 + ((lane >> 4) << 3) + (lane & 7);
    const int b_off = ((lane >> 3) & 1) * 16;                    // bytes

#pragma unroll
    for (int ks = 0; ks < 4; ++ks) {
        uint32_t ah[2][4], al[2][4];
#pragma unroll
        for (int mi = 0; mi < 2; ++mi) {
            uint32_t ad = sb + (uint32_t)((a_row + mi * 16) * AT_PITCH + ks * 32) + a_off;
            ldsm4(ah[mi], ad + AT_QH);
            ldsm4(al[mi], ad + AT_QL);
        }
#pragma unroll
        for (int bi = 0; bi < 4; ++bi) {
            uint32_t bh[4], bl[4];
            uint32_t bd = sb + (uint32_t)((b_row + bi * 16) * AT_PITCH + ks * 32) + b_off;
            ldsm4(bh, bd + AT_KH);
            ldsm4(bl, bd + AT_KL);
#pragma unroll
            for (int mi = 0; mi < 2; ++mi)
#pragma unroll
                for (int half = 0; half < 2; ++half) {
                    float* c4 = sc[mi][bi * 2 + half];
                    mma_bf16(c4, ah[mi], &bh[half * 2]);
                    mma_bf16(c4, ah[mi], &bl[half * 2]);
                    mma_bf16(c4, al[mi], &bh[half * 2]);
                }
        }
    }

    // ---- softmax over rows ----
    const int trow = lane >> 2;
    const int tcol = (lane & 3) * 2;
    float* red  = (float*)(sm + AT_RED);
    float* red2 = (float*)(sm + AT_RED2);

#pragma unroll
    for (int mi = 0; mi < 2; ++mi)
#pragma unroll
        for (int hr = 0; hr < 2; ++hr) {
            float m = -1e30f;
#pragma unroll
            for (int ni = 0; ni < 8; ++ni) {
                m = fmaxf(m, sc[mi][ni][hr * 2 + 0]);
                m = fmaxf(m, sc[mi][ni][hr * 2 + 1]);
            }
            m = fmaxf(m, __shfl_xor_sync(0xffffffffu, m, 1));
            m = fmaxf(m, __shfl_xor_sync(0xffffffffu, m, 2));
            int row = wm * 32 + mi * 16 + hr * 8 + trow;
            if ((lane & 3) == 0) red[row * 2 + wn] = m;
        }
    __syncthreads();

    float inv_[2][2];
#pragma unroll
    for (int mi = 0; mi < 2; ++mi)
#pragma unroll
        for (int hr = 0; hr < 2; ++hr) {
            int row = wm * 32 + mi * 16 + hr * 8 + trow;
            float m2 = fmaxf(red[row * 2], red[row * 2 + 1]);
            float ls = 0.f;
#pragma unroll
            for (int ni = 0; ni < 8; ++ni) {
                float e0 = fexp(sc[mi][ni][hr * 2 + 0] - m2);
                float e1 = fexp(sc[mi][ni][hr * 2 + 1] - m2);
                sc[mi][ni][hr * 2 + 0] = e0;
                sc[mi][ni][hr * 2 + 1] = e1;
                ls += e0 + e1;
            }
            ls += __shfl_xor_sync(0xffffffffu, ls, 1);
            ls += __shfl_xor_sync(0xffffffffu, ls, 2);
            if ((lane & 3) == 0) red2[row * 2 + wn] = ls;
        }
    __syncthreads();

#pragma unroll
    for (int mi = 0; mi < 2; ++mi)
#pragma unroll
        for (int hr = 0; hr < 2; ++hr) {
            int row = wm * 32 + mi * 16 + hr * 8 + trow;
            inv_[mi][hr] = 1.0f / (red2[row * 2] + red2[row * 2 + 1]);
        }

    // ---- write P (unnormalized exp) as bf16 hi/lo ----
#pragma unroll
    for (int mi = 0; mi < 2; ++mi)
#pragma unroll
        for (int hr = 0; hr < 2; ++hr) {
            int row = wm * 32 + mi * 16 + hr * 8 + trow;
            uint32_t pb = sb + (uint32_t)(row * AT_PPITCH);
#pragma unroll
            for (int ni = 0; ni < 8; ++ni) {
                float e0 = sc[mi][ni][hr * 2 + 0];
                float e1 = sc[mi][ni][hr * 2 + 1];
                uint32_t hh = bf2(e0, e1);
                float r0 = e0 - __uint_as_float(hh << 16);
                float r1 = e1 - __uint_as_float(hh & 0xffff0000u);
                uint32_t ll = bf2(r0, r1);
                int colB = (wn * 64 + ni * 8 + tcol) * 2;
                asm volatile("st.shared.u32 [%0], %1;" :: "r"(pb + AT_PH + colB), "r"(hh) : "memory");
                asm volatile("st.shared.u32 [%0], %1;" :: "r"(pb + AT_PL + colB), "r"(ll) : "memory");
            }
        }
    __syncthreads();

    // ---- PV: O = P * V  (M=128, N=64, K=128), V^T via ldmatrix.trans ----
    float oc[2][4][4];
#pragma unroll
    for (int mi = 0; mi < 2; ++mi)
#pragma unroll
        for (int ni = 0; ni < 4; ++ni)
#pragma unroll
            for (int q = 0; q < 4; ++q) oc[mi][ni][q] = 0.f;

    const int vrow_l = (lane & 7) + ((lane >> 3) & 1) * 8;   // + ks*16
    const int vcol_l = wn * 64 + ((lane >> 4) & 1) * 16;     // bytes; + p*32

#pragma unroll
    for (int ks = 0; ks < 8; ++ks) {
        uint32_t ph[2][4], pl[2][4];
#pragma unroll
        for (int mi = 0; mi < 2; ++mi) {
            uint32_t ad = sb + (uint32_t)((a_row + mi * 16) * AT_PPITCH + ks * 32) + a_off;
            ldsm4(ph[mi], ad + AT_PH);
            ldsm4(pl[mi], ad + AT_PL);
        }
#pragma unroll
        for (int p = 0; p < 2; ++p) {
            uint32_t vh4[4], vl4[4];
            uint32_t vd = sb + (uint32_t)((ks * 16 + vrow_l) * AT_PITCH) + vcol_l + p * 32;
            ldsm4t(vh4, vd + AT_VH);
            ldsm4t(vl4, vd + AT_VL);
#pragma unroll
            for (int mi = 0; mi < 2; ++mi)
#pragma unroll
                for (int half = 0; half < 2; ++half) {
                    float* c4 = oc[mi][p * 2 + half];
                    mma_bf16(c4, ph[mi], &vh4[half * 2]);
                    mma_bf16(c4, ph[mi], &vl4[half * 2]);
                    mma_bf16(c4, pl[mi], &vh4[half * 2]);
                }
        }
    }

    // ---- epilogue: normalize, split to bf16 hi/lo, store ----
#pragma unroll
    for (int mi = 0; mi < 2; ++mi)
#pragma unroll
        for (int hr = 0; hr < 2; ++hr) {
            int row = wm * 32 + mi * 16 + hr * 8 + trow;
            float iv = inv_[mi][hr];
            size_t ob = ((size_t)row * PN + n) * PD + h * PDK;
#pragma unroll
            for (int ni = 0; ni < 4; ++ni) {
                int col = wn * 32 + ni * 8 + tcol;
                float f0 = oc[mi][ni][hr * 2 + 0] * iv;
                float f1 = oc[mi][ni][hr * 2 + 1] * iv;
                uint32_t hh = bf2(f0, f1);
                float r0 = f0 - __uint_as_float(hh << 16);
                float r1 = f1 - __uint_as_float(hh & 0xffff0000u);
                *(uint32_t*)(Oh + ob + col) = hh;
                *(uint32_t*)(Ol + ob + col) = bf2(r0, r1);
            }
        }
}

// ---------------------------------------------------------------------------
extern "C" void kernel_launch(void* const* d_in, const int* in_sizes, int n_in,
                              void* d_out, int out_size)
{
    const float* query = (const float*)d_in[0];
    const float* key_i = (const float*)d_in[1];
    const float* value = (const float*)d_in[2];
    const float* Wq = (const float*)d_in[3];
    const float* bq = (const float*)d_in[4];
    const float* Wk = (const float*)d_in[5];
    const float* bk = (const float*)d_in[6];
    const float* Wv = (const float*)d_in[7];
    const float* bv = (const float*)d_in[8];
    const float* Wo = (const float*)d_in[9];
    const float* bo = (const float*)d_in[10];
    float* out = (float*)d_out;

    __nv_bfloat16 *xqh, *xql, *xkh, *xkl, *xvh, *xvl;
    __nv_bfloat16 *pqh, *pql, *pkh, *pkl, *pvh, *pvl, *ohp, *olp, *wh, *wl;
    cudaGetSymbolAddress((void**)&xqh, g_xq_h);
    cudaGetSymbolAddress((void**)&xql, g_xq_l);
    cudaGetSymbolAddress((void**)&xkh, g_xk_h);
    cudaGetSymbolAddress((void**)&xkl, g_xk_l);
    cudaGetSymbolAddress((void**)&xvh, g_xv_h);
    cudaGetSymbolAddress((void**)&xvl, g_xv_l);
    cudaGetSymbolAddress((void**)&pqh, g_pq_h);
    cudaGetSymbolAddress((void**)&pql, g_pq_l);
    cudaGetSymbolAddress((void**)&pkh, g_pk_h);
    cudaGetSymbolAddress((void**)&pkl, g_pk_l);
    cudaGetSymbolAddress((void**)&pvh, g_pv_h);
    cudaGetSymbolAddress((void**)&pvl, g_pv_l);
    cudaGetSymbolAddress((void**)&ohp, g_o_h);
    cudaGetSymbolAddress((void**)&olp, g_o_l);
    cudaGetSymbolAddress((void**)&wh,  g_wh);
    cudaGetSymbolAddress((void**)&wl,  g_wl);

    cudaFuncSetAttribute(gemm_bf16x3<true>,
                         cudaFuncAttributeMaxDynamicSharedMemorySize, GEMM_SMEM);
    cudaFuncSetAttribute(gemm_bf16x3<false>,
                         cudaFuncAttributeMaxDynamicSharedMemorySize, GEMM_SMEM);
    cudaFuncSetAttribute(attn_tc,
                         cudaFuncAttributeMaxDynamicSharedMemorySize, AT_SMEM);

    const int nbig = PM * PD / 4, nw = PD * PD / 4;
    dim3 gg(PD / 128, PM / 128);   // (8, 256)

    // batched splits: 2 launches instead of 7
    dim3 gin(nbig / 1024, 1, 3);
    split_inputs<<<gin, 256>>>(query, key_i, value,
                               xqh, xql, xkh, xkl, xvh, xvl);
    dim3 gwt(nw / 1024, 1, 4);
    split_weights<<<gwt, 256>>>(Wq, Wk, Wv, Wo, wh, wl);

    gemm_bf16x3<true><<<gg, 128, GEMM_SMEM>>>(
        xqh, xql, wh + 0 * (size_t)PD * PD, wl + 0 * (size_t)PD * PD,
        bq, 0.125f, nullptr, pqh, pql);
    gemm_bf16x3<true><<<gg, 128, GEMM_SMEM>>>(
        xkh, xkl, wh + 1 * (size_t)PD * PD, wl + 1 * (size_t)PD * PD,
        bk, 1.0f, nullptr, pkh, pkl);
    gemm_bf16x3<true><<<gg, 128, GEMM_SMEM>>>(
        xvh, xvl, wh + 2 * (size_t)PD * PD, wl + 2 * (size_t)PD * PD,
        bv, 1.0f, nullptr, pvh, pvl);

    attn_tc<<<PH * PN, 256, AT_SMEM>>>(pqh, pql, pkh, pkl, pvh, pvl, ohp, olp);

    gemm_bf16x3<false><<<gg, 128, GEMM_SMEM>>>(
        ohp, olp, wh + 3 * (size_t)PD * PD, wl + 3 * (size_t)PD * PD,
        bo, 1.0f, out, nullptr, nullptr);
}